// round 4
// baseline (speedup 1.0000x reference)
#include <cuda_runtime.h>
#include <cuda_fp16.h>
#include <math.h>
#include <stdint.h>

#define HDIM 2048
#define IDIM 2048
#define NEXP 16
#define TOPK 4
#define ALPHA 1.702f
#define LIMIT 7.0f
#define T_MAX 4096
#define BM 128
#define BN 128
#define BK 64
#define KC (HDIM/BK)              /* 32 */
#define MAX_ROWS (T_MAX*TOPK + NEXP*BM)   /* 18432 */
#define MAX_TILES (MAX_ROWS/BM)           /* 144 */

// gemm1 smem: A 2x16KB @0, B (gate16KB+up16KB) x2 @32768. total 96KB
#define ST_A 16384
#define OFF_B 32768
#define ST_B1 32768
#define SMEM1 98304
// gemm2 smem: A 2x16KB @0, B 16KB x2 @32768. total 64KB
#define ST_B2 16384
#define SMEM2 65536

// ------------------------- scratch (static device) ---------------------------
__device__ __half g_xh[(size_t)T_MAX*HDIM];          // 16 MB
__device__ __half g_acth[(size_t)MAX_ROWS*IDIM];     // 75 MB
__device__ int   g_topk_idx[T_MAX*TOPK];
__device__ float g_topk_w[T_MAX*TOPK];
__device__ int   g_cnt[NEXP];
__device__ int   g_off[NEXP];
__device__ int   g_cursor[NEXP];
__device__ int   g_pair_tok[MAX_ROWS];
__device__ float g_pair_w[MAX_ROWS];
__device__ int   g_tile_expert[MAX_TILES];

// ------------------------- asm helpers --------------------------------------
__device__ __forceinline__ uint32_t smem_u32(const void* p) {
    uint32_t a;
    asm("{ .reg .u64 t; cvta.to.shared.u64 t, %1; cvt.u32.u64 %0, t; }"
        : "=r"(a) : "l"(p));
    return a;
}
__device__ __forceinline__ uint32_t swzA(uint32_t off) {   // 128B rows
    return off ^ ((off >> 3) & 0x70);
}
__device__ __forceinline__ uint32_t swzB(uint32_t off) {   // 256B rows
    return off ^ (((off >> 8) & 7) << 4);
}
#define CP16(dst, src) \
    asm volatile("cp.async.cg.shared.global [%0], [%1], 16;\n" :: "r"(dst), "l"(src))
#define CP16Z(dst, src, sz) \
    asm volatile("cp.async.cg.shared.global [%0], [%1], 16, %2;\n" :: "r"(dst), "l"(src), "r"(sz))
#define CP_COMMIT() asm volatile("cp.async.commit_group;\n" ::: "memory")
#define CP_WAIT0() asm volatile("cp.async.wait_group 0;\n" ::: "memory")
#define LDSM4(r0,r1,r2,r3,a) \
    asm volatile("ldmatrix.sync.aligned.m8n8.x4.shared.b16 {%0,%1,%2,%3}, [%4];\n" \
        : "=r"(r0),"=r"(r1),"=r"(r2),"=r"(r3) : "r"(a))
#define LDSM4T(r0,r1,r2,r3,a) \
    asm volatile("ldmatrix.sync.aligned.m8n8.x4.trans.shared.b16 {%0,%1,%2,%3}, [%4];\n" \
        : "=r"(r0),"=r"(r1),"=r"(r2),"=r"(r3) : "r"(a))
#define MMA16816(d, a, b) \
    asm volatile("mma.sync.aligned.m16n8k16.row.col.f32.f16.f16.f32 " \
        "{%0,%1,%2,%3}, {%4,%5,%6,%7}, {%8,%9}, {%0,%1,%2,%3};\n" \
        : "+f"((d)[0]),"+f"((d)[1]),"+f"((d)[2]),"+f"((d)[3]) \
        : "r"((a)[0]),"r"((a)[1]),"r"((a)[2]),"r"((a)[3]), "r"((b)[0]),"r"((b)[1]))

__device__ __forceinline__ float actf(float g, float u) {
    g = fminf(g, LIMIT);
    u = fminf(fmaxf(u, -LIMIT), LIMIT);
    return (u + 1.f) * g / (1.f + expf(-ALPHA * g));
}
__device__ __forceinline__ uint32_t h2bits(float a, float b) {
    __half2 h = __floats2half2_rn(a, b);
    return *reinterpret_cast<uint32_t*>(&h);
}

// ---------------- init: zero counters, poison maps ---------------------------
__global__ void init_kernel()
{
    int i = blockIdx.x * blockDim.x + threadIdx.x;
    if (i < MAX_ROWS) g_pair_tok[i] = -1;
    if (i < MAX_TILES) g_tile_expert[i] = -1;
    if (i < NEXP) g_cnt[i] = 0;
}

// ---------------- router: logits + top4 + softmax + xh + counts --------------
__global__ void __launch_bounds__(128) router_kernel(
    const float* __restrict__ x, const float* __restrict__ rw,
    const float* __restrict__ rb, int T)
{
    int t = blockIdx.x;
    if (t >= T) return;
    int tid = threadIdx.x;
    int e = tid >> 3;
    int s = tid & 7;

    const float4* xr = (const float4*)(x + (size_t)t * HDIM);
    const float4* wr = (const float4*)(rw + (size_t)e * HDIM);
    float acc = 0.f;
    for (int j = s; j < HDIM/4; j += 8) {
        float4 a = xr[j], b = wr[j];
        acc += a.x*b.x + a.y*b.y + a.z*b.z + a.w*b.w;
    }
    acc += __shfl_down_sync(0xffffffffu, acc, 4, 8);
    acc += __shfl_down_sync(0xffffffffu, acc, 2, 8);
    acc += __shfl_down_sync(0xffffffffu, acc, 1, 8);

    __shared__ float s_logit[NEXP];
    if (s == 0) s_logit[e] = acc + rb[e];

    // fp16 copy of x row (L1-hot re-read)
    for (int j = tid; j < HDIM/4; j += 128) {
        float4 v = xr[j];
        uint2 o;
        o.x = h2bits(v.x, v.y);
        o.y = h2bits(v.z, v.w);
        *(uint2*)&g_xh[(size_t)t*HDIM + j*4] = o;
    }
    __syncthreads();

    if (tid == 0) {
        float v[NEXP];
        #pragma unroll
        for (int i = 0; i < NEXP; i++) v[i] = s_logit[i];
        int   bi[TOPK];
        float bv[TOPK];
        unsigned used = 0;
        #pragma unroll
        for (int k = 0; k < TOPK; k++) {
            int best = -1; float bval = -INFINITY;
            #pragma unroll
            for (int i = 0; i < NEXP; i++) {
                if (!((used >> i) & 1u) && v[i] > bval) { bval = v[i]; best = i; }
            }
            used |= (1u << best);
            bi[k] = best; bv[k] = bval;
        }
        float m = bv[0];
        float w[TOPK], sum = 0.f;
        #pragma unroll
        for (int k = 0; k < TOPK; k++) { w[k] = expf(bv[k] - m); sum += w[k]; }
        float inv = 1.f / sum;
        #pragma unroll
        for (int k = 0; k < TOPK; k++) {
            g_topk_idx[t*TOPK + k] = bi[k];
            g_topk_w[t*TOPK + k]   = w[k] * inv;
            atomicAdd(&g_cnt[bi[k]], 1);
        }
    }
}

// ---------------- offsets (BM-padded segments) + tile->expert map ------------
__global__ void offsets_kernel()
{
    int off = 0;
    for (int e = 0; e < NEXP; e++) {
        g_off[e] = off;
        g_cursor[e] = off;
        int padded = ((g_cnt[e] + BM - 1) / BM) * BM;
        for (int t = off / BM; t < (off + padded) / BM; t++) g_tile_expert[t] = e;
        off += padded;
    }
}

// ---------------- atomic-cursor compaction ------------------------------------
__global__ void __launch_bounds__(256) fill_kernel(int T)
{
    int i = blockIdx.x * 256 + threadIdx.x;
    if (i >= T * TOPK) return;
    int e = g_topk_idx[i];
    int p = atomicAdd(&g_cursor[e], 1);
    g_pair_tok[p] = i >> 2;
    g_pair_w[p]   = g_topk_w[i];
}

// ---------------- GEMM1 (mma.sync fp16, fp32 B direct load) -------------------
__global__ void __launch_bounds__(256, 1) gemm1_kernel(
    const float* __restrict__ w1f, const float* __restrict__ b1)
{
    int by = blockIdx.y;
    int e = g_tile_expert[by];
    if (e < 0) return;
    int n0 = blockIdx.x * BN;
    int row0 = by * BM;
    int tid = threadIdx.x, lane = tid & 31, wid = tid >> 5;
    int wm = wid & 1, wn = wid >> 1;
    int br = tid >> 4, bc = tid & 15;

    extern __shared__ char smem[];
    uint32_t sb = smem_u32(smem);
    __shared__ int s_tok[BM];
    if (tid < BM) s_tok[tid] = g_pair_tok[row0 + tid];
    __syncthreads();

    const float* w1e = w1f + (size_t)e * HDIM * (2*IDIM);
    const float* gcol = w1e + n0 + bc*8;
    const float* ucol = w1e + IDIM + n0 + bc*8;

    // ---- prologue: B(0) into slot0 + A(0) cp.async ----
    {
        #pragma unroll
        for (int j = 0; j < 4; j++) {
            int r = j*16 + br;
            const float4* pg = (const float4*)(gcol + (size_t)r * (2*IDIM));
            const float4* pu = (const float4*)(ucol + (size_t)r * (2*IDIM));
            float4 g0 = pg[0], g1 = pg[1], u0 = pu[0], u1 = pu[1];
            uint4 hg, hu;
            hg.x = h2bits(g0.x, g0.y); hg.y = h2bits(g0.z, g0.w);
            hg.z = h2bits(g1.x, g1.y); hg.w = h2bits(g1.z, g1.w);
            hu.x = h2bits(u0.x, u0.y); hu.y = h2bits(u0.z, u0.w);
            hu.z = h2bits(u1.x, u1.y); hu.w = h2bits(u1.z, u1.w);
            uint32_t so = swzB((uint32_t)(r*256 + bc*16));
            *(uint4*)(smem + OFF_B + so) = hg;
            *(uint4*)(smem + OFF_B + 16384 + so) = hu;
        }
        uint32_t abase = sb;
        #pragma unroll
        for (int i = 0; i < 4; i++) {
            int id = tid + i*256;
            int r = id >> 3, c = id & 7;
            int tok = s_tok[r];
            const __half* src = g_xh + (size_t)(tok < 0 ? 0 : tok)*HDIM + c*8;
            CP16Z(abase + swzA((uint32_t)(r*128 + c*16)), src, tok >= 0 ? 16 : 0);
        }
        CP_COMMIT();
    }

    float ag[4][4][4] = {}, au[4][4][4] = {};

    for (int kc = 0; kc < KC; kc++) {
        CP_WAIT0();
        __syncthreads();
        int slot = kc & 1;
        uint32_t abase = sb + slot*ST_A;
        uint32_t gbase = sb + OFF_B + slot*ST_B1;
        uint32_t ubase = gbase + 16384;
        bool more = (kc + 1 < KC);
        int nslot = (kc + 1) & 1;
        int nk0 = (kc + 1) * BK;

        float4 vg[4][2], vu[4][2];
        if (more) {
            // A(kc+1) cp.async
            uint32_t nab = sb + nslot*ST_A;
            #pragma unroll
            for (int i = 0; i < 4; i++) {
                int id = tid + i*256;
                int r = id >> 3, c = id & 7;
                int tok = s_tok[r];
                const __half* src = g_xh + (size_t)(tok < 0 ? 0 : tok)*HDIM + nk0 + c*8;
                CP16Z(nab + swzA((uint32_t)(r*128 + c*16)), src, tok >= 0 ? 16 : 0);
            }
            CP_COMMIT();
            // gate fp32 loads for kc+1
            #pragma unroll
            for (int j = 0; j < 4; j++) {
                int r = j*16 + br;
                const float4* pg = (const float4*)(gcol + (size_t)(nk0 + r) * (2*IDIM));
                vg[j][0] = pg[0]; vg[j][1] = pg[1];
            }
        }
        // MMA k16 = 0,1
        #pragma unroll
        for (int k16 = 0; k16 < 2; k16++) {
            uint32_t a[4][4];
            #pragma unroll
            for (int mt = 0; mt < 4; mt++) {
                int mrow = wm*64 + mt*16 + (lane & 15);
                LDSM4(a[mt][0], a[mt][1], a[mt][2], a[mt][3],
                      abase + swzA((uint32_t)(mrow*128 + (k16*2 + (lane>>4))*16)));
            }
            uint32_t bg[4][2], bu[4][2];
            #pragma unroll
            for (int h = 0; h < 2; h++) {
                int krow = k16*16 + (lane & 15);
                int nh = wn*32 + h*16 + (lane>>4)*8;
                uint32_t off = swzB((uint32_t)(krow*256 + nh*2));
                uint32_t r0,r1,r2,r3;
                LDSM4T(r0,r1,r2,r3, gbase + off);
                bg[h*2][0]=r0; bg[h*2][1]=r1; bg[h*2+1][0]=r2; bg[h*2+1][1]=r3;
                LDSM4T(r0,r1,r2,r3, ubase + off);
                bu[h*2][0]=r0; bu[h*2][1]=r1; bu[h*2+1][0]=r2; bu[h*2+1][1]=r3;
            }
            #pragma unroll
            for (int mt = 0; mt < 4; mt++)
                #pragma unroll
                for (int nt = 0; nt < 4; nt++) {
                    MMA16816(ag[mt][nt], a[mt], bg[nt]);
                    MMA16816(au[mt][nt], a[mt], bu[nt]);
                }
        }
        if (more) {
            // store gate, load up
            uint32_t ngb = sb + OFF_B + nslot*ST_B1;
            #pragma unroll
            for (int j = 0; j < 4; j++) {
                int r = j*16 + br;
                uint4 h;
                h.x = h2bits(vg[j][0].x, vg[j][0].y); h.y = h2bits(vg[j][0].z, vg[j][0].w);
                h.z = h2bits(vg[j][1].x, vg[j][1].y); h.w = h2bits(vg[j][1].z, vg[j][1].w);
                *(uint4*)(smem + (ngb - sb) + swzB((uint32_t)(r*256 + bc*16))) = h;
            }
            #pragma unroll
            for (int j = 0; j < 4; j++) {
                int r = j*16 + br;
                const float4* pu = (const float4*)(ucol + (size_t)(nk0 + r) * (2*IDIM));
                vu[j][0] = pu[0]; vu[j][1] = pu[1];
            }
        }
        // MMA k16 = 2,3
        #pragma unroll
        for (int k16 = 2; k16 < 4; k16++) {
            uint32_t a[4][4];
            #pragma unroll
            for (int mt = 0; mt < 4; mt++) {
                int mrow = wm*64 + mt*16 + (lane & 15);
                LDSM4(a[mt][0], a[mt][1], a[mt][2], a[mt][3],
                      abase + swzA((uint32_t)(mrow*128 + (k16*2 + (lane>>4))*16)));
            }
            uint32_t bg[4][2], bu[4][2];
            #pragma unroll
            for (int h = 0; h < 2; h++) {
                int krow = k16*16 + (lane & 15);
                int nh = wn*32 + h*16 + (lane>>4)*8;
                uint32_t off = swzB((uint32_t)(krow*256 + nh*2));
                uint32_t r0,r1,r2,r3;
                LDSM4T(r0,r1,r2,r3, gbase + off);
                bg[h*2][0]=r0; bg[h*2][1]=r1; bg[h*2+1][0]=r2; bg[h*2+1][1]=r3;
                LDSM4T(r0,r1,r2,r3, ubase + off);
                bu[h*2][0]=r0; bu[h*2][1]=r1; bu[h*2+1][0]=r2; bu[h*2+1][1]=r3;
            }
            #pragma unroll
            for (int mt = 0; mt < 4; mt++)
                #pragma unroll
                for (int nt = 0; nt < 4; nt++) {
                    MMA16816(ag[mt][nt], a[mt], bg[nt]);
                    MMA16816(au[mt][nt], a[mt], bu[nt]);
                }
        }
        if (more) {
            uint32_t nub = OFF_B + nslot*ST_B1 + 16384;
            #pragma unroll
            for (int j = 0; j < 4; j++) {
                int r = j*16 + br;
                uint4 h;
                h.x = h2bits(vu[j][0].x, vu[j][0].y); h.y = h2bits(vu[j][0].z, vu[j][0].w);
                h.z = h2bits(vu[j][1].x, vu[j][1].y); h.w = h2bits(vu[j][1].z, vu[j][1].w);
                *(uint4*)(smem + nub + swzB((uint32_t)(r*256 + bc*16))) = h;
            }
        }
    }

    // epilogue: bias + clip + glu in registers -> half2 stores
    const float* b1e = b1 + (size_t)e * (2*IDIM);
    int r0 = lane >> 2, cc = (lane & 3) * 2;
    #pragma unroll
    for (int nt = 0; nt < 4; nt++) {
        int col = n0 + wn*32 + nt*8 + cc;
        float G0 = b1e[col], G1 = b1e[col+1];
        float U0 = b1e[IDIM + col], U1 = b1e[IDIM + col + 1];
        #pragma unroll
        for (int mt = 0; mt < 4; mt++) {
            int grow = row0 + wm*64 + mt*16;
            float a0 = actf(ag[mt][nt][0] + G0, au[mt][nt][0] + U0);
            float a1 = actf(ag[mt][nt][1] + G1, au[mt][nt][1] + U1);
            float a2 = actf(ag[mt][nt][2] + G0, au[mt][nt][2] + U0);
            float a3 = actf(ag[mt][nt][3] + G1, au[mt][nt][3] + U1);
            __half2 h01 = __floats2half2_rn(a0, a1);
            __half2 h23 = __floats2half2_rn(a2, a3);
            *(__half2*)&g_acth[(size_t)(grow + r0) * IDIM + col]     = h01;
            *(__half2*)&g_acth[(size_t)(grow + r0 + 8) * IDIM + col] = h23;
        }
    }
}

// ---------------- GEMM2 (mma.sync fp16, fp32 B direct load) -------------------
__global__ void __launch_bounds__(256, 1) gemm2_kernel(
    const float* __restrict__ w2f, const float* __restrict__ b2,
    float* __restrict__ out)
{
    int by = blockIdx.y;
    int e = g_tile_expert[by];
    if (e < 0) return;
    int n0 = blockIdx.x * BN;
    int row0 = by * BM;
    int tid = threadIdx.x, lane = tid & 31, wid = tid >> 5;
    int wm = wid & 1, wn = wid >> 1;
    int br = tid >> 4, bc = tid & 15;

    extern __shared__ char smem[];
    uint32_t sb = smem_u32(smem);
    __shared__ int   s_tok[BM];
    __shared__ float s_wt[BM];
    if (tid < BM) {
        s_tok[tid] = g_pair_tok[row0 + tid];
        s_wt[tid]  = g_pair_w[row0 + tid];
    }
    __syncthreads();

    const float* w2e = w2f + (size_t)e * IDIM * HDIM;
    const float* bcol = w2e + n0 + bc*8;

    // ---- prologue ----
    {
        #pragma unroll
        for (int j = 0; j < 4; j++) {
            int r = j*16 + br;
            const float4* p = (const float4*)(bcol + (size_t)r * HDIM);
            float4 v0 = p[0], v1 = p[1];
            uint4 h;
            h.x = h2bits(v0.x, v0.y); h.y = h2bits(v0.z, v0.w);
            h.z = h2bits(v1.x, v1.y); h.w = h2bits(v1.z, v1.w);
            *(uint4*)(smem + OFF_B + swzB((uint32_t)(r*256 + bc*16))) = h;
        }
        #pragma unroll
        for (int i = 0; i < 4; i++) {
            int id = tid + i*256;
            int r = id >> 3, c = id & 7;
            const __half* src = g_acth + (size_t)(row0 + r)*IDIM + c*8;
            CP16(sb + swzA((uint32_t)(r*128 + c*16)), src);
        }
        CP_COMMIT();
    }

    float acc[4][4][4] = {};

    for (int kc = 0; kc < KC; kc++) {
        CP_WAIT0();
        __syncthreads();
        int slot = kc & 1;
        uint32_t abase = sb + slot*ST_A;
        uint32_t bbase = sb + OFF_B + slot*ST_B2;
        bool more = (kc + 1 < KC);
        int nslot = (kc + 1) & 1;
        int nk0 = (kc + 1) * BK;

        float4 vb[4][2];
        if (more) {
            uint32_t nab = sb + nslot*ST_A;
            #pragma unroll
            for (int i = 0; i < 4; i++) {
                int id = tid + i*256;
                int r = id >> 3, c = id & 7;
                const __half* src = g_acth + (size_t)(row0 + r)*IDIM + nk0 + c*8;
                CP16(nab + swzA((uint32_t)(r*128 + c*16)), src);
            }
            CP_COMMIT();
            #pragma unroll
            for (int j = 0; j < 4; j++) {
                int r = j*16 + br;
                const float4* p = (const float4*)(bcol + (size_t)(nk0 + r) * HDIM);
                vb[j][0] = p[0]; vb[j][1] = p[1];
            }
        }
        #pragma unroll
        for (int k16 = 0; k16 < 2; k16++) {
            uint32_t a[4][4];
            #pragma unroll
            for (int mt = 0; mt < 4; mt++) {
                int mrow = wm*64 + mt*16 + (lane & 15);
                LDSM4(a[mt][0], a[mt][1], a[mt][2], a[mt][3],
                      abase + swzA((uint32_t)(mrow*128 + (k16*2 + (lane>>4))*16)));
            }
            uint32_t b[4][2];
            #pragma unroll
            for (int h = 0; h < 2; h++) {
                int krow = k16*16 + (lane & 15);
                int nh = wn*32 + h*16 + (lane>>4)*8;
                uint32_t r0,r1,r2,r3;
                LDSM4T(r0,r1,r2,r3, bbase + swzB((uint32_t)(krow*256 + nh*2)));
                b[h*2][0]=r0; b[h*2][1]=r1; b[h*2+1][0]=r2; b[h*2+1][1]=r3;
            }
            #pragma unroll
            for (int mt = 0; mt < 4; mt++)
                #pragma unroll
                for (int nt = 0; nt < 4; nt++)
                    MMA16816(acc[mt][nt], a[mt], b[nt]);
        }
        if (more) {
            uint32_t nbb = OFF_B + nslot*ST_B2;
            #pragma unroll
            for (int j = 0; j < 4; j++) {
                int r = j*16 + br;
                uint4 h;
                h.x = h2bits(vb[j][0].x, vb[j][0].y); h.y = h2bits(vb[j][0].z, vb[j][0].w);
                h.z = h2bits(vb[j][1].x, vb[j][1].y); h.w = h2bits(vb[j][1].z, vb[j][1].w);
                *(uint4*)(smem + nbb + swzB((uint32_t)(r*256 + bc*16))) = h;
            }
        }
        #pragma unroll
        for (int k16 = 2; k16 < 4; k16++) {
            uint32_t a[4][4];
            #pragma unroll
            for (int mt = 0; mt < 4; mt++) {
                int mrow = wm*64 + mt*16 + (lane & 15);
                LDSM4(a[mt][0], a[mt][1], a[mt][2], a[mt][3],
                      abase + swzA((uint32_t)(mrow*128 + (k16*2 + (lane>>4))*16)));
            }
            uint32_t b[4][2];
            #pragma unroll
            for (int h = 0; h < 2; h++) {
                int krow = k16*16 + (lane & 15);
                int nh = wn*32 + h*16 + (lane>>4)*8;
                uint32_t r0,r1,r2,r3;
                LDSM4T(r0,r1,r2,r3, bbase + swzB((uint32_t)(krow*256 + nh*2)));
                b[h*2][0]=r0; b[h*2][1]=r1; b[h*2+1][0]=r2; b[h*2+1][1]=r3;
            }
            #pragma unroll
            for (int mt = 0; mt < 4; mt++)
                #pragma unroll
                for (int nt = 0; nt < 4; nt++)
                    MMA16816(acc[mt][nt], a[mt], b[nt]);
        }
    }

    // epilogue: +bias, *routing weight, atomic scatter by token
    const float* b2e = b2 + (size_t)e * HDIM;
    int r0 = lane >> 2, cc = (lane & 3) * 2;
    #pragma unroll
    for (int mt = 0; mt < 4; mt++) {
        int mrow = wm*64 + mt*16;
        int rA = mrow + r0, rB = rA + 8;
        int tokA = s_tok[rA], tokB = s_tok[rB];
        float wA = s_wt[rA], wB = s_wt[rB];
        #pragma unroll
        for (int nt = 0; nt < 4; nt++) {
            int col = n0 + wn*32 + nt*8 + cc;
            float B0 = b2e[col], B1 = b2e[col+1];
            if (tokA >= 0) {
                atomicAdd(&out[(size_t)tokA * HDIM + col],     (acc[mt][nt][0] + B0) * wA);
                atomicAdd(&out[(size_t)tokA * HDIM + col + 1], (acc[mt][nt][1] + B1) * wA);
            }
            if (tokB >= 0) {
                atomicAdd(&out[(size_t)tokB * HDIM + col],     (acc[mt][nt][2] + B0) * wB);
                atomicAdd(&out[(size_t)tokB * HDIM + col + 1], (acc[mt][nt][3] + B1) * wB);
            }
        }
    }
}

// ---------------- launch ------------------------------------------------------
extern "C" void kernel_launch(void* const* d_in, const int* in_sizes, int n_in,
                              void* d_out, int out_size)
{
    const float* x  = (const float*)d_in[0];
    const float* rw = (const float*)d_in[1];
    const float* rb = (const float*)d_in[2];
    const float* w1 = (const float*)d_in[3];
    const float* b1 = (const float*)d_in[4];
    const float* w2 = (const float*)d_in[5];
    const float* b2 = (const float*)d_in[6];
    float* out = (float*)d_out;

    int T = in_sizes[0] / HDIM;
    if (T > T_MAX) T = T_MAX;

    cudaFuncSetAttribute(gemm1_kernel, cudaFuncAttributeMaxDynamicSharedMemorySize, SMEM1);
    cudaFuncSetAttribute(gemm2_kernel, cudaFuncAttributeMaxDynamicSharedMemorySize, SMEM2);

    cudaMemsetAsync(out, 0, (size_t)T * HDIM * sizeof(float));

    init_kernel<<<(MAX_ROWS + 255)/256, 256>>>();
    router_kernel<<<T, 128>>>(x, rw, rb, T);
    offsets_kernel<<<1, 1>>>();
    fill_kernel<<<(T*TOPK + 255)/256, 256>>>(T);
    gemm1_kernel<<<dim3(IDIM/BN, MAX_TILES), 256, SMEM1>>>(w1, b1);
    gemm2_kernel<<<dim3(HDIM/BN, MAX_TILES), 256, SMEM2>>>(w2, b2, out);
}

// round 5
// speedup vs baseline: 1.1632x; 1.1632x over previous
#include <cuda_runtime.h>
#include <cuda_fp16.h>
#include <math.h>
#include <stdint.h>

#define HDIM 2048
#define IDIM 2048
#define NEXP 16
#define TOPK 4
#define ALPHA 1.702f
#define LIMIT 7.0f
#define T_MAX 4096
#define BM 128
#define BN 128
#define BK 64
#define KC (HDIM/BK)              /* 32 */
#define NSTAGE 4
#define MAX_ROWS (T_MAX*TOPK + NEXP*BM)   /* 18432 */
#define MAX_TILES (MAX_ROWS/BM)           /* 144 */

// gemm1 smem: A 4x16KB @0, B (gate16KB+up16KB) x4 @65536. total 192KB
#define ST_A 16384
#define OFF_B1 65536
#define ST_B1 32768
#define SMEM1 196608
// gemm2 smem: A 4x16KB @0, B 16KB x4 @65536. total 128KB
#define OFF_B2 65536
#define ST_B2 16384
#define SMEM2 131072

// ------------------------- scratch (static device) ---------------------------
__device__ __half g_w1h[(size_t)NEXP*HDIM*2*IDIM];   // 268 MB
__device__ __half g_w2h[(size_t)NEXP*IDIM*HDIM];     // 134 MB
__device__ __half g_xh[(size_t)T_MAX*HDIM];          // 16 MB
__device__ __half g_acth[(size_t)MAX_ROWS*IDIM];     // 75 MB
__device__ int   g_topk_idx[T_MAX*TOPK];
__device__ float g_topk_w[T_MAX*TOPK];
__device__ int   g_cnt[NEXP];
__device__ int   g_off[NEXP];
__device__ int   g_cursor[NEXP];
__device__ int   g_pair_tok[MAX_ROWS];
__device__ float g_pair_w[MAX_ROWS];
__device__ int   g_tile_expert[MAX_TILES];

// ------------------------- asm helpers --------------------------------------
__device__ __forceinline__ uint32_t smem_u32(const void* p) {
    uint32_t a;
    asm("{ .reg .u64 t; cvta.to.shared.u64 t, %1; cvt.u32.u64 %0, t; }"
        : "=r"(a) : "l"(p));
    return a;
}
__device__ __forceinline__ uint32_t swzA(uint32_t off) {   // 128B rows
    return off ^ ((off >> 3) & 0x70);
}
__device__ __forceinline__ uint32_t swzB(uint32_t off) {   // 256B rows
    return off ^ (((off >> 8) & 7) << 4);
}
#define CP16(dst, src) \
    asm volatile("cp.async.cg.shared.global [%0], [%1], 16;\n" :: "r"(dst), "l"(src))
#define CP16Z(dst, src, sz) \
    asm volatile("cp.async.cg.shared.global [%0], [%1], 16, %2;\n" :: "r"(dst), "l"(src), "r"(sz))
#define CP_COMMIT() asm volatile("cp.async.commit_group;\n" ::: "memory")
#define CP_WAIT2() asm volatile("cp.async.wait_group 2;\n" ::: "memory")
#define CP_WAIT1() asm volatile("cp.async.wait_group 1;\n" ::: "memory")
#define CP_WAIT0() asm volatile("cp.async.wait_group 0;\n" ::: "memory")
#define LDSM4(r0,r1,r2,r3,a) \
    asm volatile("ldmatrix.sync.aligned.m8n8.x4.shared.b16 {%0,%1,%2,%3}, [%4];\n" \
        : "=r"(r0),"=r"(r1),"=r"(r2),"=r"(r3) : "r"(a))
#define LDSM4T(r0,r1,r2,r3,a) \
    asm volatile("ldmatrix.sync.aligned.m8n8.x4.trans.shared.b16 {%0,%1,%2,%3}, [%4];\n" \
        : "=r"(r0),"=r"(r1),"=r"(r2),"=r"(r3) : "r"(a))
#define MMA16816(d, a, b) \
    asm volatile("mma.sync.aligned.m16n8k16.row.col.f32.f16.f16.f32 " \
        "{%0,%1,%2,%3}, {%4,%5,%6,%7}, {%8,%9}, {%0,%1,%2,%3};\n" \
        : "+f"((d)[0]),"+f"((d)[1]),"+f"((d)[2]),"+f"((d)[3]) \
        : "r"((a)[0]),"r"((a)[1]),"r"((a)[2]),"r"((a)[3]), "r"((b)[0]),"r"((b)[1]))

__device__ __forceinline__ float actf(float g, float u) {
    g = fminf(g, LIMIT);
    u = fminf(fmaxf(u, -LIMIT), LIMIT);
    return (u + 1.f) * g / (1.f + expf(-ALPHA * g));
}
__device__ __forceinline__ uint32_t h2bits(float a, float b) {
    __half2 h = __floats2half2_rn(a, b);
    return *reinterpret_cast<uint32_t*>(&h);
}

// ---------------- fp32 -> fp16 conversion ------------------------------------
__global__ void __launch_bounds__(256) cvt_kernel(const float4* __restrict__ src,
                                                  uint2* __restrict__ dst, int n)
{
    int i = blockIdx.x * blockDim.x + threadIdx.x;
    int stride = gridDim.x * blockDim.x;
    for (; i < n; i += stride) {
        float4 v = src[i];
        uint2 o;
        o.x = h2bits(v.x, v.y);
        o.y = h2bits(v.z, v.w);
        dst[i] = o;
    }
}

// ---------------- init: poison maps, zero counters ----------------------------
__global__ void init_kernel()
{
    int i = blockIdx.x * blockDim.x + threadIdx.x;
    if (i < MAX_ROWS) g_pair_tok[i] = -1;
    if (i < MAX_TILES) g_tile_expert[i] = -1;
    if (i < NEXP) g_cnt[i] = 0;
}

// ---------------- router: logits + top4 + softmax + xh + counts --------------
__global__ void __launch_bounds__(128) router_kernel(
    const float* __restrict__ x, const float* __restrict__ rw,
    const float* __restrict__ rb, int T)
{
    int t = blockIdx.x;
    if (t >= T) return;
    int tid = threadIdx.x;
    int e = tid >> 3;
    int s = tid & 7;

    const float4* xr = (const float4*)(x + (size_t)t * HDIM);
    const float4* wr = (const float4*)(rw + (size_t)e * HDIM);
    float acc = 0.f;
    for (int j = s; j < HDIM/4; j += 8) {
        float4 a = xr[j], b = wr[j];
        acc += a.x*b.x + a.y*b.y + a.z*b.z + a.w*b.w;
    }
    acc += __shfl_down_sync(0xffffffffu, acc, 4, 8);
    acc += __shfl_down_sync(0xffffffffu, acc, 2, 8);
    acc += __shfl_down_sync(0xffffffffu, acc, 1, 8);

    __shared__ float s_logit[NEXP];
    if (s == 0) s_logit[e] = acc + rb[e];

    // fp16 copy of x row (re-read is L1/L2-hot)
    for (int j = tid; j < HDIM/4; j += 128) {
        float4 v = xr[j];
        uint2 o;
        o.x = h2bits(v.x, v.y);
        o.y = h2bits(v.z, v.w);
        *(uint2*)&g_xh[(size_t)t*HDIM + j*4] = o;
    }
    __syncthreads();

    if (tid == 0) {
        float v[NEXP];
        #pragma unroll
        for (int i = 0; i < NEXP; i++) v[i] = s_logit[i];
        int   bi[TOPK];
        float bv[TOPK];
        unsigned used = 0;
        #pragma unroll
        for (int k = 0; k < TOPK; k++) {
            int best = -1; float bval = -INFINITY;
            #pragma unroll
            for (int i = 0; i < NEXP; i++) {
                if (!((used >> i) & 1u) && v[i] > bval) { bval = v[i]; best = i; }
            }
            used |= (1u << best);
            bi[k] = best; bv[k] = bval;
        }
        float m = bv[0];
        float w[TOPK], sum = 0.f;
        #pragma unroll
        for (int k = 0; k < TOPK; k++) { w[k] = expf(bv[k] - m); sum += w[k]; }
        float inv = 1.f / sum;
        #pragma unroll
        for (int k = 0; k < TOPK; k++) {
            g_topk_idx[t*TOPK + k] = bi[k];
            g_topk_w[t*TOPK + k]   = w[k] * inv;
            atomicAdd(&g_cnt[bi[k]], 1);
        }
    }
}

// ---------------- offsets (BM-padded segments) + tile->expert map ------------
__global__ void offsets_kernel()
{
    int off = 0;
    for (int e = 0; e < NEXP; e++) {
        g_off[e] = off;
        g_cursor[e] = off;
        int padded = ((g_cnt[e] + BM - 1) / BM) * BM;
        for (int t = off / BM; t < (off + padded) / BM; t++) g_tile_expert[t] = e;
        off += padded;
    }
}

// ---------------- atomic-cursor compaction ------------------------------------
__global__ void __launch_bounds__(256) fill_kernel(int T)
{
    int i = blockIdx.x * 256 + threadIdx.x;
    if (i >= T * TOPK) return;
    int e = g_topk_idx[i];
    int p = atomicAdd(&g_cursor[e], 1);
    g_pair_tok[p] = i >> 2;
    g_pair_w[p]   = g_topk_w[i];
}

// ---------------- GEMM1 (mma.sync fp16): acth = glu(x @ w1 + b1) -------------
__global__ void __launch_bounds__(256, 1) gemm1_kernel(const float* __restrict__ b1)
{
    int by = blockIdx.y;
    int e = g_tile_expert[by];
    if (e < 0) return;
    int n0 = blockIdx.x * BN;
    int row0 = by * BM;
    int tid = threadIdx.x, lane = tid & 31, wid = tid >> 5;
    int wm = wid & 1, wn = wid >> 1;

    extern __shared__ char smem[];
    uint32_t sb = smem_u32(smem);
    __shared__ int s_tok[BM];
    if (tid < BM) s_tok[tid] = g_pair_tok[row0 + tid];
    __syncthreads();

    const __half* w1e = g_w1h + (size_t)e * HDIM * (2*IDIM);

    auto issue = [&](int kc) {
        int slot = kc % NSTAGE;
        uint32_t abase = sb + slot * ST_A;
        uint32_t gbase = sb + OFF_B1 + slot * ST_B1;
        uint32_t ubase = gbase + 16384;
        int k0 = kc * BK;
        #pragma unroll
        for (int i = 0; i < 4; i++) {
            int id = tid + i * 256;
            int r = id >> 3, c = id & 7;
            int tok = s_tok[r];
            const __half* src = g_xh + (size_t)(tok < 0 ? 0 : tok) * HDIM + k0 + c*8;
            int sz = (tok >= 0) ? 16 : 0;
            CP16Z(abase + swzA((uint32_t)(r*128 + c*16)), src, sz);
        }
        #pragma unroll
        for (int i = 0; i < 4; i++) {
            int id = tid + i * 256;
            int r = id >> 4, c = id & 15;
            const __half* srcg = w1e + (size_t)(k0 + r) * (2*IDIM) + n0 + c*8;
            uint32_t off = swzB((uint32_t)(r*256 + c*16));
            CP16(gbase + off, srcg);
            CP16(ubase + off, srcg + IDIM);
        }
        CP_COMMIT();
    };

    float ag[4][4][4] = {}, au[4][4][4] = {};
    issue(0); issue(1); issue(2);

    for (int kc = 0; kc < KC; kc++) {
        int slot = kc % NSTAGE;
        if (kc >= KC - 1) { CP_WAIT0(); }
        else if (kc >= KC - 2) { CP_WAIT1(); }
        else { CP_WAIT2(); }
        __syncthreads();
        uint32_t abase = sb + slot * ST_A;
        uint32_t gbase = sb + OFF_B1 + slot * ST_B1;
        uint32_t ubase = gbase + 16384;
        #pragma unroll
        for (int k16 = 0; k16 < 4; k16++) {
            uint32_t a[4][4];
            #pragma unroll
            for (int mt = 0; mt < 4; mt++) {
                int mrow = wm*64 + mt*16 + (lane & 15);
                uint32_t addr = abase + swzA((uint32_t)(mrow*128 + (k16*2 + (lane>>4))*16));
                LDSM4(a[mt][0], a[mt][1], a[mt][2], a[mt][3], addr);
            }
            uint32_t bg[4][2], bu[4][2];
            #pragma unroll
            for (int h = 0; h < 2; h++) {
                int krow = k16*16 + (lane & 15);
                int nh = wn*32 + h*16 + (lane>>4)*8;
                uint32_t off = swzB((uint32_t)(krow*256 + nh*2));
                uint32_t r0,r1,r2,r3;
                LDSM4T(r0,r1,r2,r3, gbase + off);
                bg[h*2][0]=r0; bg[h*2][1]=r1; bg[h*2+1][0]=r2; bg[h*2+1][1]=r3;
                LDSM4T(r0,r1,r2,r3, ubase + off);
                bu[h*2][0]=r0; bu[h*2][1]=r1; bu[h*2+1][0]=r2; bu[h*2+1][1]=r3;
            }
            #pragma unroll
            for (int mt = 0; mt < 4; mt++)
                #pragma unroll
                for (int nt = 0; nt < 4; nt++) {
                    MMA16816(ag[mt][nt], a[mt], bg[nt]);
                    MMA16816(au[mt][nt], a[mt], bu[nt]);
                }
        }
        if (kc + 3 < KC) issue(kc + 3);
    }

    // epilogue: bias + clip + glu in registers -> half2 stores
    const float* b1e = b1 + (size_t)e * (2*IDIM);
    int r0 = lane >> 2, cc = (lane & 3) * 2;
    #pragma unroll
    for (int nt = 0; nt < 4; nt++) {
        int col = n0 + wn*32 + nt*8 + cc;
        float G0 = b1e[col], G1 = b1e[col+1];
        float U0 = b1e[IDIM + col], U1 = b1e[IDIM + col + 1];
        #pragma unroll
        for (int mt = 0; mt < 4; mt++) {
            int grow = row0 + wm*64 + mt*16;
            float a0 = actf(ag[mt][nt][0] + G0, au[mt][nt][0] + U0);
            float a1 = actf(ag[mt][nt][1] + G1, au[mt][nt][1] + U1);
            float a2 = actf(ag[mt][nt][2] + G0, au[mt][nt][2] + U0);
            float a3 = actf(ag[mt][nt][3] + G1, au[mt][nt][3] + U1);
            __half2 h01 = __floats2half2_rn(a0, a1);
            __half2 h23 = __floats2half2_rn(a2, a3);
            *(__half2*)&g_acth[(size_t)(grow + r0) * IDIM + col]     = h01;
            *(__half2*)&g_acth[(size_t)(grow + r0 + 8) * IDIM + col] = h23;
        }
    }
}

// ---------------- GEMM2 (mma.sync fp16): out += w * (acth @ w2 + b2) ---------
__global__ void __launch_bounds__(256, 1) gemm2_kernel(const float* __restrict__ b2,
                                                       float* __restrict__ out)
{
    int by = blockIdx.y;
    int e = g_tile_expert[by];
    if (e < 0) return;
    int n0 = blockIdx.x * BN;
    int row0 = by * BM;
    int tid = threadIdx.x, lane = tid & 31, wid = tid >> 5;
    int wm = wid & 1, wn = wid >> 1;

    extern __shared__ char smem[];
    uint32_t sb = smem_u32(smem);
    __shared__ int   s_tok[BM];
    __shared__ float s_wt[BM];
    if (tid < BM) {
        s_tok[tid] = g_pair_tok[row0 + tid];
        s_wt[tid]  = g_pair_w[row0 + tid];
    }
    __syncthreads();

    const __half* w2e = g_w2h + (size_t)e * IDIM * HDIM;

    auto issue = [&](int kc) {
        int slot = kc % NSTAGE;
        uint32_t abase = sb + slot * ST_A;
        uint32_t bbase = sb + OFF_B2 + slot * ST_B2;
        int k0 = kc * BK;
        #pragma unroll
        for (int i = 0; i < 4; i++) {
            int id = tid + i * 256;
            int r = id >> 3, c = id & 7;
            const __half* src = g_acth + (size_t)(row0 + r) * IDIM + k0 + c*8;
            CP16(abase + swzA((uint32_t)(r*128 + c*16)), src);
        }
        #pragma unroll
        for (int i = 0; i < 4; i++) {
            int id = tid + i * 256;
            int r = id >> 4, c = id & 15;
            const __half* src = w2e + (size_t)(k0 + r) * HDIM + n0 + c*8;
            CP16(bbase + swzB((uint32_t)(r*256 + c*16)), src);
        }
        CP_COMMIT();
    };

    float acc[4][4][4] = {};
    issue(0); issue(1); issue(2);

    for (int kc = 0; kc < KC; kc++) {
        int slot = kc % NSTAGE;
        if (kc >= KC - 1) { CP_WAIT0(); }
        else if (kc >= KC - 2) { CP_WAIT1(); }
        else { CP_WAIT2(); }
        __syncthreads();
        uint32_t abase = sb + slot * ST_A;
        uint32_t bbase = sb + OFF_B2 + slot * ST_B2;
        #pragma unroll
        for (int k16 = 0; k16 < 4; k16++) {
            uint32_t a[4][4];
            #pragma unroll
            for (int mt = 0; mt < 4; mt++) {
                int mrow = wm*64 + mt*16 + (lane & 15);
                uint32_t addr = abase + swzA((uint32_t)(mrow*128 + (k16*2 + (lane>>4))*16));
                LDSM4(a[mt][0], a[mt][1], a[mt][2], a[mt][3], addr);
            }
            uint32_t b[4][2];
            #pragma unroll
            for (int h = 0; h < 2; h++) {
                int krow = k16*16 + (lane & 15);
                int nh = wn*32 + h*16 + (lane>>4)*8;
                uint32_t off = swzB((uint32_t)(krow*256 + nh*2));
                uint32_t r0,r1,r2,r3;
                LDSM4T(r0,r1,r2,r3, bbase + off);
                b[h*2][0]=r0; b[h*2][1]=r1; b[h*2+1][0]=r2; b[h*2+1][1]=r3;
            }
            #pragma unroll
            for (int mt = 0; mt < 4; mt++)
                #pragma unroll
                for (int nt = 0; nt < 4; nt++)
                    MMA16816(acc[mt][nt], a[mt], b[nt]);
        }
        if (kc + 3 < KC) issue(kc + 3);
    }

    // epilogue: +bias, *routing weight, atomic scatter by token
    const float* b2e = b2 + (size_t)e * HDIM;
    int r0 = lane >> 2, cc = (lane & 3) * 2;
    #pragma unroll
    for (int mt = 0; mt < 4; mt++) {
        int mrow = wm*64 + mt*16;
        int rA = mrow + r0, rB = rA + 8;
        int tokA = s_tok[rA], tokB = s_tok[rB];
        float wA = s_wt[rA], wB = s_wt[rB];
        #pragma unroll
        for (int nt = 0; nt < 4; nt++) {
            int col = n0 + wn*32 + nt*8 + cc;
            float B0 = b2e[col], B1 = b2e[col+1];
            if (tokA >= 0) {
                atomicAdd(&out[(size_t)tokA * HDIM + col],     (acc[mt][nt][0] + B0) * wA);
                atomicAdd(&out[(size_t)tokA * HDIM + col + 1], (acc[mt][nt][1] + B1) * wA);
            }
            if (tokB >= 0) {
                atomicAdd(&out[(size_t)tokB * HDIM + col],     (acc[mt][nt][2] + B0) * wB);
                atomicAdd(&out[(size_t)tokB * HDIM + col + 1], (acc[mt][nt][3] + B1) * wB);
            }
        }
    }
}

// ---------------- launch ------------------------------------------------------
extern "C" void kernel_launch(void* const* d_in, const int* in_sizes, int n_in,
                              void* d_out, int out_size)
{
    const float* x  = (const float*)d_in[0];
    const float* rw = (const float*)d_in[1];
    const float* rb = (const float*)d_in[2];
    const float* w1 = (const float*)d_in[3];
    const float* b1 = (const float*)d_in[4];
    const float* w2 = (const float*)d_in[5];
    const float* b2 = (const float*)d_in[6];
    float* out = (float*)d_out;

    int T = in_sizes[0] / HDIM;
    if (T > T_MAX) T = T_MAX;

    cudaFuncSetAttribute(gemm1_kernel, cudaFuncAttributeMaxDynamicSharedMemorySize, SMEM1);
    cudaFuncSetAttribute(gemm2_kernel, cudaFuncAttributeMaxDynamicSharedMemorySize, SMEM2);

    __half *w1h_p, *w2h_p;
    cudaGetSymbolAddress((void**)&w1h_p, g_w1h);
    cudaGetSymbolAddress((void**)&w2h_p, g_w2h);

    cudaMemsetAsync(out, 0, (size_t)T * HDIM * sizeof(float));

    init_kernel<<<(MAX_ROWS + 255)/256, 256>>>();
    router_kernel<<<T, 128>>>(x, rw, rb, T);
    offsets_kernel<<<1, 1>>>();
    fill_kernel<<<(T*TOPK + 255)/256, 256>>>(T);
    cvt_kernel<<<2048, 256>>>((const float4*)w1, (uint2*)w1h_p, NEXP*HDIM*2*IDIM/4);
    cvt_kernel<<<2048, 256>>>((const float4*)w2, (uint2*)w2h_p, NEXP*IDIM*HDIM/4);
    gemm1_kernel<<<dim3(IDIM/BN, MAX_TILES), 256, SMEM1>>>(b1);
    gemm2_kernel<<<dim3(HDIM/BN, MAX_TILES), 256, SMEM2>>>(b2, out);
}

// round 6
// speedup vs baseline: 1.1804x; 1.0148x over previous
#include <cuda_runtime.h>
#include <cuda_fp16.h>
#include <math.h>
#include <stdint.h>

#define HDIM 2048
#define IDIM 2048
#define NEXP 16
#define TOPK 4
#define ALPHA 1.702f
#define LIMIT 7.0f
#define T_MAX 4096
#define BM 128
#define BN 128
#define BK 64
#define KC (HDIM/BK)              /* 32 */
#define NSTAGE 4
#define MAX_ROWS (T_MAX*TOPK + NEXP*BM)   /* 18432 */
#define MAX_TILES (MAX_ROWS/BM)           /* 144 */

// gemm1 smem: A 4x16KB @0, B (gate16KB+up16KB) x4 @65536. total 192KB
#define ST_A 16384
#define OFF_B1 65536
#define ST_B1 32768
#define SMEM1 196608
// gemm2 smem: A 4x16KB @0, B 16KB x4 @65536. total 128KB
#define OFF_B2 65536
#define ST_B2 16384
#define SMEM2 131072

// ------------------------- scratch (static device) ---------------------------
__device__ __half g_w1h[(size_t)NEXP*HDIM*2*IDIM];   // 268 MB
__device__ __half g_w2h[(size_t)NEXP*IDIM*HDIM];     // 134 MB
__device__ __half g_xh[(size_t)T_MAX*HDIM];          // 16 MB
__device__ __half g_acth[(size_t)MAX_ROWS*IDIM];     // 75 MB
__device__ int   g_topk_idx[T_MAX*TOPK];
__device__ float g_topk_w[T_MAX*TOPK];
__device__ int   g_cnt[NEXP];
__device__ int   g_off[NEXP];
__device__ int   g_cursor[NEXP];
__device__ int   g_pair_tok[MAX_ROWS];
__device__ float g_pair_w[MAX_ROWS];
__device__ int   g_tile_expert[MAX_TILES];

// ------------------------- asm helpers --------------------------------------
__device__ __forceinline__ uint32_t smem_u32(const void* p) {
    uint32_t a;
    asm("{ .reg .u64 t; cvta.to.shared.u64 t, %1; cvt.u32.u64 %0, t; }"
        : "=r"(a) : "l"(p));
    return a;
}
__device__ __forceinline__ uint32_t swzA(uint32_t off) {   // 128B rows
    return off ^ ((off >> 3) & 0x70);
}
__device__ __forceinline__ uint32_t swzB(uint32_t off) {   // 256B rows
    return off ^ (((off >> 8) & 7) << 4);
}
#define CP16(dst, src) \
    asm volatile("cp.async.cg.shared.global [%0], [%1], 16;\n" :: "r"(dst), "l"(src))
#define CP16Z(dst, src, sz) \
    asm volatile("cp.async.cg.shared.global [%0], [%1], 16, %2;\n" :: "r"(dst), "l"(src), "r"(sz))
#define CP_COMMIT() asm volatile("cp.async.commit_group;\n" ::: "memory")
#define CP_WAIT2() asm volatile("cp.async.wait_group 2;\n" ::: "memory")
#define CP_WAIT1() asm volatile("cp.async.wait_group 1;\n" ::: "memory")
#define CP_WAIT0() asm volatile("cp.async.wait_group 0;\n" ::: "memory")
#define LDSM4(r0,r1,r2,r3,a) \
    asm volatile("ldmatrix.sync.aligned.m8n8.x4.shared.b16 {%0,%1,%2,%3}, [%4];\n" \
        : "=r"(r0),"=r"(r1),"=r"(r2),"=r"(r3) : "r"(a))
#define LDSM4T(r0,r1,r2,r3,a) \
    asm volatile("ldmatrix.sync.aligned.m8n8.x4.trans.shared.b16 {%0,%1,%2,%3}, [%4];\n" \
        : "=r"(r0),"=r"(r1),"=r"(r2),"=r"(r3) : "r"(a))
#define MMA16816(d, a, b) \
    asm volatile("mma.sync.aligned.m16n8k16.row.col.f32.f16.f16.f32 " \
        "{%0,%1,%2,%3}, {%4,%5,%6,%7}, {%8,%9}, {%0,%1,%2,%3};\n" \
        : "+f"((d)[0]),"+f"((d)[1]),"+f"((d)[2]),"+f"((d)[3]) \
        : "r"((a)[0]),"r"((a)[1]),"r"((a)[2]),"r"((a)[3]), "r"((b)[0]),"r"((b)[1]))

__device__ __forceinline__ float actf(float g, float u) {
    g = fminf(g, LIMIT);
    u = fminf(fmaxf(u, -LIMIT), LIMIT);
    return (u + 1.f) * g / (1.f + expf(-ALPHA * g));
}
__device__ __forceinline__ uint32_t h2bits(float a, float b) {
    __half2 h = __floats2half2_rn(a, b);
    return *reinterpret_cast<uint32_t*>(&h);
}

// ---------------- fp32 -> fp16 conversion ------------------------------------
__global__ void __launch_bounds__(256) cvt_kernel(const float4* __restrict__ src,
                                                  uint2* __restrict__ dst, int n)
{
    int i = blockIdx.x * blockDim.x + threadIdx.x;
    int stride = gridDim.x * blockDim.x;
    for (; i < n; i += stride) {
        float4 v = src[i];
        uint2 o;
        o.x = h2bits(v.x, v.y);
        o.y = h2bits(v.z, v.w);
        dst[i] = o;
    }
}

// ---------------- init: poison maps, zero counters ----------------------------
__global__ void init_kernel()
{
    int i = blockIdx.x * blockDim.x + threadIdx.x;
    if (i < MAX_ROWS) g_pair_tok[i] = -1;
    if (i < MAX_TILES) g_tile_expert[i] = -1;
    if (i < NEXP) g_cnt[i] = 0;
}

// ---------------- router: logits + top4 + softmax + xh + counts --------------
__global__ void __launch_bounds__(128) router_kernel(
    const float* __restrict__ x, const float* __restrict__ rw,
    const float* __restrict__ rb, int T)
{
    int t = blockIdx.x;
    if (t >= T) return;
    int tid = threadIdx.x;
    int e = tid >> 3;
    int s = tid & 7;

    const float4* xr = (const float4*)(x + (size_t)t * HDIM);
    const float4* wr = (const float4*)(rw + (size_t)e * HDIM);
    float acc = 0.f;
    for (int j = s; j < HDIM/4; j += 8) {
        float4 a = xr[j], b = wr[j];
        acc += a.x*b.x + a.y*b.y + a.z*b.z + a.w*b.w;
    }
    acc += __shfl_down_sync(0xffffffffu, acc, 4, 8);
    acc += __shfl_down_sync(0xffffffffu, acc, 2, 8);
    acc += __shfl_down_sync(0xffffffffu, acc, 1, 8);

    __shared__ float s_logit[NEXP];
    if (s == 0) s_logit[e] = acc + rb[e];

    // fp16 copy of x row (re-read is L1/L2-hot)
    for (int j = tid; j < HDIM/4; j += 128) {
        float4 v = xr[j];
        uint2 o;
        o.x = h2bits(v.x, v.y);
        o.y = h2bits(v.z, v.w);
        *(uint2*)&g_xh[(size_t)t*HDIM + j*4] = o;
    }
    __syncthreads();

    if (tid == 0) {
        float v[NEXP];
        #pragma unroll
        for (int i = 0; i < NEXP; i++) v[i] = s_logit[i];
        int   bi[TOPK];
        float bv[TOPK];
        unsigned used = 0;
        #pragma unroll
        for (int k = 0; k < TOPK; k++) {
            int best = -1; float bval = -INFINITY;
            #pragma unroll
            for (int i = 0; i < NEXP; i++) {
                if (!((used >> i) & 1u) && v[i] > bval) { bval = v[i]; best = i; }
            }
            used |= (1u << best);
            bi[k] = best; bv[k] = bval;
        }
        float m = bv[0];
        float w[TOPK], sum = 0.f;
        #pragma unroll
        for (int k = 0; k < TOPK; k++) { w[k] = expf(bv[k] - m); sum += w[k]; }
        float inv = 1.f / sum;
        #pragma unroll
        for (int k = 0; k < TOPK; k++) {
            g_topk_idx[t*TOPK + k] = bi[k];
            g_topk_w[t*TOPK + k]   = w[k] * inv;
            atomicAdd(&g_cnt[bi[k]], 1);
        }
    }
}

// ---------------- offsets (BM-padded segments) + tile->expert map ------------
__global__ void offsets_kernel()
{
    int off = 0;
    for (int e = 0; e < NEXP; e++) {
        g_off[e] = off;
        g_cursor[e] = off;
        int padded = ((g_cnt[e] + BM - 1) / BM) * BM;
        for (int t = off / BM; t < (off + padded) / BM; t++) g_tile_expert[t] = e;
        off += padded;
    }
}

// ---------------- atomic-cursor compaction ------------------------------------
__global__ void __launch_bounds__(256) fill_kernel(int T)
{
    int i = blockIdx.x * 256 + threadIdx.x;
    if (i >= T * TOPK) return;
    int e = g_topk_idx[i];
    int p = atomicAdd(&g_cursor[e], 1);
    g_pair_tok[p] = i >> 2;
    g_pair_w[p]   = g_topk_w[i];
}

// ---------------- GEMM1 (mma.sync fp16): acth = glu(x @ w1 + b1) -------------
__global__ void __launch_bounds__(256, 1) gemm1_kernel(const float* __restrict__ b1)
{
    int by = blockIdx.y;
    int e = g_tile_expert[by];
    if (e < 0) return;
    int n0 = blockIdx.x * BN;
    int row0 = by * BM;
    int tid = threadIdx.x, lane = tid & 31, wid = tid >> 5;
    int wm = wid & 1, wn = wid >> 1;

    extern __shared__ char smem[];
    uint32_t sb = smem_u32(smem);
    __shared__ int s_tok[BM];
    if (tid < BM) s_tok[tid] = g_pair_tok[row0 + tid];
    __syncthreads();

    const __half* w1e = g_w1h + (size_t)e * HDIM * (2*IDIM);

    auto issue = [&](int kc) {
        int slot = kc % NSTAGE;
        uint32_t abase = sb + slot * ST_A;
        uint32_t gbase = sb + OFF_B1 + slot * ST_B1;
        uint32_t ubase = gbase + 16384;
        int k0 = kc * BK;
        #pragma unroll
        for (int i = 0; i < 4; i++) {
            int id = tid + i * 256;
            int r = id >> 3, c = id & 7;
            int tok = s_tok[r];
            const __half* src = g_xh + (size_t)(tok < 0 ? 0 : tok) * HDIM + k0 + c*8;
            int sz = (tok >= 0) ? 16 : 0;
            CP16Z(abase + swzA((uint32_t)(r*128 + c*16)), src, sz);
        }
        #pragma unroll
        for (int i = 0; i < 4; i++) {
            int id = tid + i * 256;
            int r = id >> 4, c = id & 15;
            const __half* srcg = w1e + (size_t)(k0 + r) * (2*IDIM) + n0 + c*8;
            uint32_t off = swzB((uint32_t)(r*256 + c*16));
            CP16(gbase + off, srcg);
            CP16(ubase + off, srcg + IDIM);
        }
        CP_COMMIT();
    };

    float ag[4][4][4] = {}, au[4][4][4] = {};
    issue(0); issue(1); issue(2);

    for (int kc = 0; kc < KC; kc++) {
        int slot = kc % NSTAGE;
        if (kc >= KC - 1) { CP_WAIT0(); }
        else if (kc >= KC - 2) { CP_WAIT1(); }
        else { CP_WAIT2(); }
        __syncthreads();
        uint32_t abase = sb + slot * ST_A;
        uint32_t gbase = sb + OFF_B1 + slot * ST_B1;
        uint32_t ubase = gbase + 16384;
        #pragma unroll
        for (int k16 = 0; k16 < 4; k16++) {
            uint32_t a[4][4];
            #pragma unroll
            for (int mt = 0; mt < 4; mt++) {
                int mrow = wm*64 + mt*16 + (lane & 15);
                uint32_t addr = abase + swzA((uint32_t)(mrow*128 + (k16*2 + (lane>>4))*16));
                LDSM4(a[mt][0], a[mt][1], a[mt][2], a[mt][3], addr);
            }
            uint32_t bg[4][2], bu[4][2];
            #pragma unroll
            for (int h = 0; h < 2; h++) {
                int krow = k16*16 + (lane & 15);
                int nh = wn*32 + h*16 + (lane>>4)*8;
                uint32_t off = swzB((uint32_t)(krow*256 + nh*2));
                uint32_t r0,r1,r2,r3;
                LDSM4T(r0,r1,r2,r3, gbase + off);
                bg[h*2][0]=r0; bg[h*2][1]=r1; bg[h*2+1][0]=r2; bg[h*2+1][1]=r3;
                LDSM4T(r0,r1,r2,r3, ubase + off);
                bu[h*2][0]=r0; bu[h*2][1]=r1; bu[h*2+1][0]=r2; bu[h*2+1][1]=r3;
            }
            #pragma unroll
            for (int mt = 0; mt < 4; mt++)
                #pragma unroll
                for (int nt = 0; nt < 4; nt++) {
                    MMA16816(ag[mt][nt], a[mt], bg[nt]);
                    MMA16816(au[mt][nt], a[mt], bu[nt]);
                }
        }
        if (kc + 3 < KC) issue(kc + 3);
    }

    // epilogue: bias + clip + glu in registers -> half2 stores
    const float* b1e = b1 + (size_t)e * (2*IDIM);
    int r0 = lane >> 2, cc = (lane & 3) * 2;
    #pragma unroll
    for (int nt = 0; nt < 4; nt++) {
        int col = n0 + wn*32 + nt*8 + cc;
        float G0 = b1e[col], G1 = b1e[col+1];
        float U0 = b1e[IDIM + col], U1 = b1e[IDIM + col + 1];
        #pragma unroll
        for (int mt = 0; mt < 4; mt++) {
            int grow = row0 + wm*64 + mt*16;
            float a0 = actf(ag[mt][nt][0] + G0, au[mt][nt][0] + U0);
            float a1 = actf(ag[mt][nt][1] + G1, au[mt][nt][1] + U1);
            float a2 = actf(ag[mt][nt][2] + G0, au[mt][nt][2] + U0);
            float a3 = actf(ag[mt][nt][3] + G1, au[mt][nt][3] + U1);
            __half2 h01 = __floats2half2_rn(a0, a1);
            __half2 h23 = __floats2half2_rn(a2, a3);
            *(__half2*)&g_acth[(size_t)(grow + r0) * IDIM + col]     = h01;
            *(__half2*)&g_acth[(size_t)(grow + r0 + 8) * IDIM + col] = h23;
        }
    }
}

// ---------------- GEMM2 (mma.sync fp16): out += w * (acth @ w2 + b2) ---------
__global__ void __launch_bounds__(256, 1) gemm2_kernel(const float* __restrict__ b2,
                                                       float* __restrict__ out)
{
    int by = blockIdx.y;
    int e = g_tile_expert[by];
    if (e < 0) return;
    int n0 = blockIdx.x * BN;
    int row0 = by * BM;
    int tid = threadIdx.x, lane = tid & 31, wid = tid >> 5;
    int wm = wid & 1, wn = wid >> 1;

    extern __shared__ char smem[];
    uint32_t sb = smem_u32(smem);
    __shared__ int   s_tok[BM];
    __shared__ float s_wt[BM];
    if (tid < BM) {
        s_tok[tid] = g_pair_tok[row0 + tid];
        s_wt[tid]  = g_pair_w[row0 + tid];
    }
    __syncthreads();

    const __half* w2e = g_w2h + (size_t)e * IDIM * HDIM;

    auto issue = [&](int kc) {
        int slot = kc % NSTAGE;
        uint32_t abase = sb + slot * ST_A;
        uint32_t bbase = sb + OFF_B2 + slot * ST_B2;
        int k0 = kc * BK;
        #pragma unroll
        for (int i = 0; i < 4; i++) {
            int id = tid + i * 256;
            int r = id >> 3, c = id & 7;
            const __half* src = g_acth + (size_t)(row0 + r) * IDIM + k0 + c*8;
            CP16(abase + swzA((uint32_t)(r*128 + c*16)), src);
        }
        #pragma unroll
        for (int i = 0; i < 4; i++) {
            int id = tid + i * 256;
            int r = id >> 4, c = id & 15;
            const __half* src = w2e + (size_t)(k0 + r) * HDIM + n0 + c*8;
            CP16(bbase + swzB((uint32_t)(r*256 + c*16)), src);
        }
        CP_COMMIT();
    };

    float acc[4][4][4] = {};
    issue(0); issue(1); issue(2);

    for (int kc = 0; kc < KC; kc++) {
        int slot = kc % NSTAGE;
        if (kc >= KC - 1) { CP_WAIT0(); }
        else if (kc >= KC - 2) { CP_WAIT1(); }
        else { CP_WAIT2(); }
        __syncthreads();
        uint32_t abase = sb + slot * ST_A;
        uint32_t bbase = sb + OFF_B2 + slot * ST_B2;
        #pragma unroll
        for (int k16 = 0; k16 < 4; k16++) {
            uint32_t a[4][4];
            #pragma unroll
            for (int mt = 0; mt < 4; mt++) {
                int mrow = wm*64 + mt*16 + (lane & 15);
                uint32_t addr = abase + swzA((uint32_t)(mrow*128 + (k16*2 + (lane>>4))*16));
                LDSM4(a[mt][0], a[mt][1], a[mt][2], a[mt][3], addr);
            }
            uint32_t b[4][2];
            #pragma unroll
            for (int h = 0; h < 2; h++) {
                int krow = k16*16 + (lane & 15);
                int nh = wn*32 + h*16 + (lane>>4)*8;
                uint32_t off = swzB((uint32_t)(krow*256 + nh*2));
                uint32_t r0,r1,r2,r3;
                LDSM4T(r0,r1,r2,r3, bbase + off);
                b[h*2][0]=r0; b[h*2][1]=r1; b[h*2+1][0]=r2; b[h*2+1][1]=r3;
            }
            #pragma unroll
            for (int mt = 0; mt < 4; mt++)
                #pragma unroll
                for (int nt = 0; nt < 4; nt++)
                    MMA16816(acc[mt][nt], a[mt], b[nt]);
        }
        if (kc + 3 < KC) issue(kc + 3);
    }

    // epilogue: +bias, *routing weight, atomic scatter by token
    const float* b2e = b2 + (size_t)e * HDIM;
    int r0 = lane >> 2, cc = (lane & 3) * 2;
    #pragma unroll
    for (int mt = 0; mt < 4; mt++) {
        int mrow = wm*64 + mt*16;
        int rA = mrow + r0, rB = rA + 8;
        int tokA = s_tok[rA], tokB = s_tok[rB];
        float wA = s_wt[rA], wB = s_wt[rB];
        #pragma unroll
        for (int nt = 0; nt < 4; nt++) {
            int col = n0 + wn*32 + nt*8 + cc;
            float B0 = b2e[col], B1 = b2e[col+1];
            if (tokA >= 0) {
                atomicAdd(&out[(size_t)tokA * HDIM + col],     (acc[mt][nt][0] + B0) * wA);
                atomicAdd(&out[(size_t)tokA * HDIM + col + 1], (acc[mt][nt][1] + B1) * wA);
            }
            if (tokB >= 0) {
                atomicAdd(&out[(size_t)tokB * HDIM + col],     (acc[mt][nt][2] + B0) * wB);
                atomicAdd(&out[(size_t)tokB * HDIM + col + 1], (acc[mt][nt][3] + B1) * wB);
            }
        }
    }
}

// ---------------- launch ------------------------------------------------------
extern "C" void kernel_launch(void* const* d_in, const int* in_sizes, int n_in,
                              void* d_out, int out_size)
{
    const float* x  = (const float*)d_in[0];
    const float* rw = (const float*)d_in[1];
    const float* rb = (const float*)d_in[2];
    const float* w1 = (const float*)d_in[3];
    const float* b1 = (const float*)d_in[4];
    const float* w2 = (const float*)d_in[5];
    const float* b2 = (const float*)d_in[6];
    float* out = (float*)d_out;

    int T = in_sizes[0] / HDIM;
    if (T > T_MAX) T = T_MAX;

    // one-time host-side resources (created on the uncaptured correctness call)
    static cudaStream_t s2 = nullptr;
    static cudaEvent_t evFork = nullptr, ev1 = nullptr, ev2 = nullptr;
    if (s2 == nullptr) {
        cudaStreamCreateWithFlags(&s2, cudaStreamNonBlocking);
        cudaEventCreateWithFlags(&evFork, cudaEventDisableTiming);
        cudaEventCreateWithFlags(&ev1, cudaEventDisableTiming);
        cudaEventCreateWithFlags(&ev2, cudaEventDisableTiming);
    }

    cudaFuncSetAttribute(gemm1_kernel, cudaFuncAttributeMaxDynamicSharedMemorySize, SMEM1);
    cudaFuncSetAttribute(gemm2_kernel, cudaFuncAttributeMaxDynamicSharedMemorySize, SMEM2);

    __half *w1h_p, *w2h_p;
    cudaGetSymbolAddress((void**)&w1h_p, g_w1h);
    cudaGetSymbolAddress((void**)&w2h_p, g_w2h);

    // ---- fork: weight conversion on side stream ----
    cudaEventRecord(evFork, 0);
    cudaStreamWaitEvent(s2, evFork, 0);
    cvt_kernel<<<2048, 256, 0, s2>>>((const float4*)w1, (uint2*)w1h_p, NEXP*HDIM*2*IDIM/4);
    cudaEventRecord(ev1, s2);
    cvt_kernel<<<2048, 256, 0, s2>>>((const float4*)w2, (uint2*)w2h_p, NEXP*IDIM*HDIM/4);
    cudaEventRecord(ev2, s2);

    // ---- main stream: routing chain ----
    cudaMemsetAsync(out, 0, (size_t)T * HDIM * sizeof(float));
    init_kernel<<<(MAX_ROWS + 255)/256, 256>>>();
    router_kernel<<<T, 128>>>(x, rw, rb, T);
    offsets_kernel<<<1, 1>>>();
    fill_kernel<<<(T*TOPK + 255)/256, 256>>>(T);

    // ---- join: gemm1 needs w1h; gemm2 additionally needs w2h ----
    cudaStreamWaitEvent(0, ev1, 0);
    gemm1_kernel<<<dim3(IDIM/BN, MAX_TILES), 256, SMEM1>>>(b1);
    cudaStreamWaitEvent(0, ev2, 0);
    gemm2_kernel<<<dim3(HDIM/BN, MAX_TILES), 256, SMEM2>>>(b2, out);
}

// round 7
// speedup vs baseline: 1.3293x; 1.1261x over previous
#include <cuda_runtime.h>
#include <cuda_fp16.h>
#include <math.h>
#include <stdint.h>

#define HDIM 2048
#define IDIM 2048
#define NEXP 16
#define TOPK 4
#define ALPHA 1.702f
#define LIMIT 7.0f
#define T_MAX 4096
#define BM 128
#define BN1 64
#define BN2 128
#define BK 64
#define KC (HDIM/BK)              /* 32 */
#define NSTAGE 3
#define MAX_ROWS (T_MAX*TOPK + NEXP*BM)   /* 18432 */
#define MAX_TILES (MAX_ROWS/BM)           /* 144 */

// gemm1 smem: A 3x16KB @0, B (gate8KB+up8KB) x3 @49152. total 96KB -> 2 CTA/SM
#define ST_A 16384
#define OFF_B1 49152
#define ST_B1 16384
#define SMEM1 98304
// gemm2 smem: A 3x16KB @0, B 16KB x3 @49152. total 96KB -> 2 CTA/SM
#define OFF_B2 49152
#define ST_B2 16384
#define SMEM2 98304

// ------------------------- scratch (static device) ---------------------------
__device__ __half g_w1h[(size_t)NEXP*HDIM*2*IDIM];   // 268 MB
__device__ __half g_w2h[(size_t)NEXP*IDIM*HDIM];     // 134 MB
__device__ __half g_xh[(size_t)T_MAX*HDIM];          // 16 MB
__device__ __half g_acth[(size_t)MAX_ROWS*IDIM];     // 75 MB
__device__ int   g_topk_idx[T_MAX*TOPK];
__device__ float g_topk_w[T_MAX*TOPK];
__device__ int   g_cnt[NEXP];
__device__ int   g_off[NEXP];
__device__ int   g_cursor[NEXP];
__device__ int   g_pair_tok[MAX_ROWS];
__device__ float g_pair_w[MAX_ROWS];
__device__ int   g_tile_expert[MAX_TILES];

// ------------------------- asm helpers --------------------------------------
__device__ __forceinline__ uint32_t smem_u32(const void* p) {
    uint32_t a;
    asm("{ .reg .u64 t; cvta.to.shared.u64 t, %1; cvt.u32.u64 %0, t; }"
        : "=r"(a) : "l"(p));
    return a;
}
__device__ __forceinline__ uint32_t swzA(uint32_t off) {   // 128B rows
    return off ^ ((off >> 3) & 0x70);
}
__device__ __forceinline__ uint32_t swzB(uint32_t off) {   // 256B rows
    return off ^ (((off >> 8) & 7) << 4);
}
#define CP16(dst, src) \
    asm volatile("cp.async.cg.shared.global [%0], [%1], 16;\n" :: "r"(dst), "l"(src))
#define CP16Z(dst, src, sz) \
    asm volatile("cp.async.cg.shared.global [%0], [%1], 16, %2;\n" :: "r"(dst), "l"(src), "r"(sz))
#define CP_COMMIT() asm volatile("cp.async.commit_group;\n" ::: "memory")
#define CP_WAIT1() asm volatile("cp.async.wait_group 1;\n" ::: "memory")
#define CP_WAIT0() asm volatile("cp.async.wait_group 0;\n" ::: "memory")
#define LDSM4(r0,r1,r2,r3,a) \
    asm volatile("ldmatrix.sync.aligned.m8n8.x4.shared.b16 {%0,%1,%2,%3}, [%4];\n" \
        : "=r"(r0),"=r"(r1),"=r"(r2),"=r"(r3) : "r"(a))
#define LDSM4T(r0,r1,r2,r3,a) \
    asm volatile("ldmatrix.sync.aligned.m8n8.x4.trans.shared.b16 {%0,%1,%2,%3}, [%4];\n" \
        : "=r"(r0),"=r"(r1),"=r"(r2),"=r"(r3) : "r"(a))
#define MMA16816(d, a, b) \
    asm volatile("mma.sync.aligned.m16n8k16.row.col.f32.f16.f16.f32 " \
        "{%0,%1,%2,%3}, {%4,%5,%6,%7}, {%8,%9}, {%0,%1,%2,%3};\n" \
        : "+f"((d)[0]),"+f"((d)[1]),"+f"((d)[2]),"+f"((d)[3]) \
        : "r"((a)[0]),"r"((a)[1]),"r"((a)[2]),"r"((a)[3]), "r"((b)[0]),"r"((b)[1]))

__device__ __forceinline__ float actf(float g, float u) {
    g = fminf(g, LIMIT);
    u = fminf(fmaxf(u, -LIMIT), LIMIT);
    return (u + 1.f) * g / (1.f + expf(-ALPHA * g));
}
__device__ __forceinline__ uint32_t h2bits(float a, float b) {
    __half2 h = __floats2half2_rn(a, b);
    return *reinterpret_cast<uint32_t*>(&h);
}

// ---------------- fp32 -> fp16 conversion ------------------------------------
__global__ void __launch_bounds__(256) cvt_kernel(const float4* __restrict__ src,
                                                  uint2* __restrict__ dst, int n)
{
    int i = blockIdx.x * blockDim.x + threadIdx.x;
    int stride = gridDim.x * blockDim.x;
    for (; i < n; i += stride) {
        float4 v = src[i];
        uint2 o;
        o.x = h2bits(v.x, v.y);
        o.y = h2bits(v.z, v.w);
        dst[i] = o;
    }
}

// ---------------- init: poison maps, zero counters ----------------------------
__global__ void init_kernel()
{
    int i = blockIdx.x * blockDim.x + threadIdx.x;
    if (i < MAX_ROWS) g_pair_tok[i] = -1;
    if (i < MAX_TILES) g_tile_expert[i] = -1;
    if (i < NEXP) g_cnt[i] = 0;
}

// ---------------- router v2: warp-per-token ----------------------------------
__global__ void __launch_bounds__(256) router_kernel(
    const float* __restrict__ x, const float* __restrict__ rw,
    const float* __restrict__ rb, int T)
{
    int t = blockIdx.x * 8 + (threadIdx.x >> 5);
    int lane = threadIdx.x & 31;
    if (t >= T) return;

    const float4* xr = (const float4*)(x + (size_t)t * HDIM);
    float acc[NEXP];
    #pragma unroll
    for (int e = 0; e < NEXP; e++) acc[e] = 0.f;

    for (int i = 0; i < 16; i++) {
        int idx = i*32 + lane;
        float4 v = xr[idx];
        uint2 o;
        o.x = h2bits(v.x, v.y);
        o.y = h2bits(v.z, v.w);
        *(uint2*)&g_xh[(size_t)t*HDIM + idx*4] = o;
        #pragma unroll
        for (int e = 0; e < NEXP; e++) {
            float4 w = ((const float4*)(rw + (size_t)e*HDIM))[idx];
            acc[e] += v.x*w.x + v.y*w.y + v.z*w.z + v.w*w.w;
        }
    }
    #pragma unroll
    for (int e = 0; e < NEXP; e++) {
        #pragma unroll
        for (int s = 16; s > 0; s >>= 1)
            acc[e] += __shfl_xor_sync(0xffffffffu, acc[e], s);
    }

    if (lane == 0) {
        float v[NEXP];
        #pragma unroll
        for (int e = 0; e < NEXP; e++) v[e] = acc[e] + rb[e];
        int   bi[TOPK];
        float bv[TOPK];
        unsigned used = 0;
        #pragma unroll
        for (int k = 0; k < TOPK; k++) {
            int best = -1; float bval = -INFINITY;
            #pragma unroll
            for (int i = 0; i < NEXP; i++) {
                if (!((used >> i) & 1u) && v[i] > bval) { bval = v[i]; best = i; }
            }
            used |= (1u << best);
            bi[k] = best; bv[k] = bval;
        }
        float m = bv[0];
        float w[TOPK], sum = 0.f;
        #pragma unroll
        for (int k = 0; k < TOPK; k++) { w[k] = expf(bv[k] - m); sum += w[k]; }
        float inv = 1.f / sum;
        #pragma unroll
        for (int k = 0; k < TOPK; k++) {
            g_topk_idx[t*TOPK + k] = bi[k];
            g_topk_w[t*TOPK + k]   = w[k] * inv;
            atomicAdd(&g_cnt[bi[k]], 1);
        }
    }
}

// ---------------- offsets (BM-padded segments) + tile->expert map ------------
__global__ void offsets_kernel()
{
    int off = 0;
    for (int e = 0; e < NEXP; e++) {
        g_off[e] = off;
        g_cursor[e] = off;
        int padded = ((g_cnt[e] + BM - 1) / BM) * BM;
        for (int t = off / BM; t < (off + padded) / BM; t++) g_tile_expert[t] = e;
        off += padded;
    }
}

// ---------------- atomic-cursor compaction ------------------------------------
__global__ void __launch_bounds__(256) fill_kernel(int T)
{
    int i = blockIdx.x * 256 + threadIdx.x;
    if (i >= T * TOPK) return;
    int e = g_topk_idx[i];
    int p = atomicAdd(&g_cursor[e], 1);
    g_pair_tok[p] = i >> 2;
    g_pair_w[p]   = g_topk_w[i];
}

// ---------------- GEMM1 (mma.sync fp16, BN=64, 2 CTA/SM) ----------------------
__global__ void __launch_bounds__(256, 2) gemm1_kernel(const float* __restrict__ b1)
{
    int by = blockIdx.y;
    int e = g_tile_expert[by];
    if (e < 0) return;
    int n0 = blockIdx.x * BN1;
    int row0 = by * BM;
    int tid = threadIdx.x, lane = tid & 31, wid = tid >> 5;
    int wm = wid & 1, wn = wid >> 1;   // wn in 0..3, warp tile 64x16

    extern __shared__ char smem[];
    uint32_t sb = smem_u32(smem);
    __shared__ int s_tok[BM];
    if (tid < BM) s_tok[tid] = g_pair_tok[row0 + tid];
    __syncthreads();

    const __half* w1e = g_w1h + (size_t)e * HDIM * (2*IDIM);

    auto issue = [&](int kc) {
        int slot = kc % NSTAGE;
        uint32_t abase = sb + slot * ST_A;
        uint32_t gbase = sb + OFF_B1 + slot * ST_B1;
        uint32_t ubase = gbase + 8192;
        int k0 = kc * BK;
        #pragma unroll
        for (int i = 0; i < 4; i++) {
            int id = tid + i * 256;
            int r = id >> 3, c = id & 7;
            int tok = s_tok[r];
            const __half* src = g_xh + (size_t)(tok < 0 ? 0 : tok) * HDIM + k0 + c*8;
            int sz = (tok >= 0) ? 16 : 0;
            CP16Z(abase + swzA((uint32_t)(r*128 + c*16)), src, sz);
        }
        #pragma unroll
        for (int i = 0; i < 2; i++) {
            int id = tid + i * 256;
            int r = id >> 3, c = id & 7;   // r: k row 0..63, c: 8-col group
            const __half* srcg = w1e + (size_t)(k0 + r) * (2*IDIM) + n0 + c*8;
            uint32_t off = swzA((uint32_t)(r*128 + c*16));
            CP16(gbase + off, srcg);
            CP16(ubase + off, srcg + IDIM);
        }
        CP_COMMIT();
    };

    float ag[4][2][4] = {}, au[4][2][4] = {};
    issue(0); issue(1);

    for (int kc = 0; kc < KC; kc++) {
        int slot = kc % NSTAGE;
        if (kc >= KC - 2) { CP_WAIT0(); } else { CP_WAIT1(); }
        __syncthreads();
        uint32_t abase = sb + slot * ST_A;
        uint32_t gbase = sb + OFF_B1 + slot * ST_B1;
        uint32_t ubase = gbase + 8192;
        #pragma unroll
        for (int k16 = 0; k16 < 4; k16++) {
            uint32_t a[4][4];
            #pragma unroll
            for (int mt = 0; mt < 4; mt++) {
                int mrow = wm*64 + mt*16 + (lane & 15);
                uint32_t addr = abase + swzA((uint32_t)(mrow*128 + (k16*2 + (lane>>4))*16));
                LDSM4(a[mt][0], a[mt][1], a[mt][2], a[mt][3], addr);
            }
            uint32_t bg[2][2], bu[2][2];
            {
                int krow = k16*16 + (lane & 15);
                int nh = wn*16 + (lane>>4)*8;
                uint32_t off = swzA((uint32_t)(krow*128 + nh*2));
                uint32_t r0,r1,r2,r3;
                LDSM4T(r0,r1,r2,r3, gbase + off);
                bg[0][0]=r0; bg[0][1]=r1; bg[1][0]=r2; bg[1][1]=r3;
                LDSM4T(r0,r1,r2,r3, ubase + off);
                bu[0][0]=r0; bu[0][1]=r1; bu[1][0]=r2; bu[1][1]=r3;
            }
            #pragma unroll
            for (int mt = 0; mt < 4; mt++)
                #pragma unroll
                for (int nt = 0; nt < 2; nt++) {
                    MMA16816(ag[mt][nt], a[mt], bg[nt]);
                    MMA16816(au[mt][nt], a[mt], bu[nt]);
                }
        }
        if (kc + 2 < KC) issue(kc + 2);
    }

    // epilogue: bias + clip + glu in registers -> half2 stores
    const float* b1e = b1 + (size_t)e * (2*IDIM);
    int r0 = lane >> 2, cc = (lane & 3) * 2;
    #pragma unroll
    for (int nt = 0; nt < 2; nt++) {
        int col = n0 + wn*16 + nt*8 + cc;
        float G0 = b1e[col], G1 = b1e[col+1];
        float U0 = b1e[IDIM + col], U1 = b1e[IDIM + col + 1];
        #pragma unroll
        for (int mt = 0; mt < 4; mt++) {
            int grow = row0 + wm*64 + mt*16;
            float a0 = actf(ag[mt][nt][0] + G0, au[mt][nt][0] + U0);
            float a1 = actf(ag[mt][nt][1] + G1, au[mt][nt][1] + U1);
            float a2 = actf(ag[mt][nt][2] + G0, au[mt][nt][2] + U0);
            float a3 = actf(ag[mt][nt][3] + G1, au[mt][nt][3] + U1);
            __half2 h01 = __floats2half2_rn(a0, a1);
            __half2 h23 = __floats2half2_rn(a2, a3);
            *(__half2*)&g_acth[(size_t)(grow + r0) * IDIM + col]     = h01;
            *(__half2*)&g_acth[(size_t)(grow + r0 + 8) * IDIM + col] = h23;
        }
    }
}

// ---------------- GEMM2 (mma.sync fp16, 3 stages, 2 CTA/SM) -------------------
__global__ void __launch_bounds__(256, 2) gemm2_kernel(const float* __restrict__ b2,
                                                       float* __restrict__ out)
{
    int by = blockIdx.y;
    int e = g_tile_expert[by];
    if (e < 0) return;
    int n0 = blockIdx.x * BN2;
    int row0 = by * BM;
    int tid = threadIdx.x, lane = tid & 31, wid = tid >> 5;
    int wm = wid & 1, wn = wid >> 1;

    extern __shared__ char smem[];
    uint32_t sb = smem_u32(smem);
    __shared__ int   s_tok[BM];
    __shared__ float s_wt[BM];
    if (tid < BM) {
        s_tok[tid] = g_pair_tok[row0 + tid];
        s_wt[tid]  = g_pair_w[row0 + tid];
    }
    __syncthreads();

    const __half* w2e = g_w2h + (size_t)e * IDIM * HDIM;

    auto issue = [&](int kc) {
        int slot = kc % NSTAGE;
        uint32_t abase = sb + slot * ST_A;
        uint32_t bbase = sb + OFF_B2 + slot * ST_B2;
        int k0 = kc * BK;
        #pragma unroll
        for (int i = 0; i < 4; i++) {
            int id = tid + i * 256;
            int r = id >> 3, c = id & 7;
            const __half* src = g_acth + (size_t)(row0 + r) * IDIM + k0 + c*8;
            CP16(abase + swzA((uint32_t)(r*128 + c*16)), src);
        }
        #pragma unroll
        for (int i = 0; i < 4; i++) {
            int id = tid + i * 256;
            int r = id >> 4, c = id & 15;
            const __half* src = w2e + (size_t)(k0 + r) * HDIM + n0 + c*8;
            CP16(bbase + swzB((uint32_t)(r*256 + c*16)), src);
        }
        CP_COMMIT();
    };

    float acc[4][4][4] = {};
    issue(0); issue(1);

    for (int kc = 0; kc < KC; kc++) {
        int slot = kc % NSTAGE;
        if (kc >= KC - 2) { CP_WAIT0(); } else { CP_WAIT1(); }
        __syncthreads();
        uint32_t abase = sb + slot * ST_A;
        uint32_t bbase = sb + OFF_B2 + slot * ST_B2;
        #pragma unroll
        for (int k16 = 0; k16 < 4; k16++) {
            uint32_t a[4][4];
            #pragma unroll
            for (int mt = 0; mt < 4; mt++) {
                int mrow = wm*64 + mt*16 + (lane & 15);
                uint32_t addr = abase + swzA((uint32_t)(mrow*128 + (k16*2 + (lane>>4))*16));
                LDSM4(a[mt][0], a[mt][1], a[mt][2], a[mt][3], addr);
            }
            uint32_t b[4][2];
            #pragma unroll
            for (int h = 0; h < 2; h++) {
                int krow = k16*16 + (lane & 15);
                int nh = wn*32 + h*16 + (lane>>4)*8;
                uint32_t off = swzB((uint32_t)(krow*256 + nh*2));
                uint32_t r0,r1,r2,r3;
                LDSM4T(r0,r1,r2,r3, bbase + off);
                b[h*2][0]=r0; b[h*2][1]=r1; b[h*2+1][0]=r2; b[h*2+1][1]=r3;
            }
            #pragma unroll
            for (int mt = 0; mt < 4; mt++)
                #pragma unroll
                for (int nt = 0; nt < 4; nt++)
                    MMA16816(acc[mt][nt], a[mt], b[nt]);
        }
        if (kc + 2 < KC) issue(kc + 2);
    }

    // epilogue: +bias, *routing weight, atomic scatter by token
    const float* b2e = b2 + (size_t)e * HDIM;
    int r0 = lane >> 2, cc = (lane & 3) * 2;
    #pragma unroll
    for (int mt = 0; mt < 4; mt++) {
        int mrow = wm*64 + mt*16;
        int rA = mrow + r0, rB = rA + 8;
        int tokA = s_tok[rA], tokB = s_tok[rB];
        float wA = s_wt[rA], wB = s_wt[rB];
        #pragma unroll
        for (int nt = 0; nt < 4; nt++) {
            int col = n0 + wn*32 + nt*8 + cc;
            float B0 = b2e[col], B1 = b2e[col+1];
            if (tokA >= 0) {
                atomicAdd(&out[(size_t)tokA * HDIM + col],     (acc[mt][nt][0] + B0) * wA);
                atomicAdd(&out[(size_t)tokA * HDIM + col + 1], (acc[mt][nt][1] + B1) * wA);
            }
            if (tokB >= 0) {
                atomicAdd(&out[(size_t)tokB * HDIM + col],     (acc[mt][nt][2] + B0) * wB);
                atomicAdd(&out[(size_t)tokB * HDIM + col + 1], (acc[mt][nt][3] + B1) * wB);
            }
        }
    }
}

// ---------------- launch ------------------------------------------------------
extern "C" void kernel_launch(void* const* d_in, const int* in_sizes, int n_in,
                              void* d_out, int out_size)
{
    const float* x  = (const float*)d_in[0];
    const float* rw = (const float*)d_in[1];
    const float* rb = (const float*)d_in[2];
    const float* w1 = (const float*)d_in[3];
    const float* b1 = (const float*)d_in[4];
    const float* w2 = (const float*)d_in[5];
    const float* b2 = (const float*)d_in[6];
    float* out = (float*)d_out;

    int T = in_sizes[0] / HDIM;
    if (T > T_MAX) T = T_MAX;

    static cudaStream_t s2 = nullptr;
    static cudaEvent_t evFork = nullptr, ev1 = nullptr, ev2 = nullptr;
    if (s2 == nullptr) {
        cudaStreamCreateWithFlags(&s2, cudaStreamNonBlocking);
        cudaEventCreateWithFlags(&evFork, cudaEventDisableTiming);
        cudaEventCreateWithFlags(&ev1, cudaEventDisableTiming);
        cudaEventCreateWithFlags(&ev2, cudaEventDisableTiming);
    }

    cudaFuncSetAttribute(gemm1_kernel, cudaFuncAttributeMaxDynamicSharedMemorySize, SMEM1);
    cudaFuncSetAttribute(gemm2_kernel, cudaFuncAttributeMaxDynamicSharedMemorySize, SMEM2);

    __half *w1h_p, *w2h_p;
    cudaGetSymbolAddress((void**)&w1h_p, g_w1h);
    cudaGetSymbolAddress((void**)&w2h_p, g_w2h);

    // ---- fork: weight conversion on side stream ----
    cudaEventRecord(evFork, 0);
    cudaStreamWaitEvent(s2, evFork, 0);
    cvt_kernel<<<2048, 256, 0, s2>>>((const float4*)w1, (uint2*)w1h_p, NEXP*HDIM*2*IDIM/4);
    cudaEventRecord(ev1, s2);
    cvt_kernel<<<2048, 256, 0, s2>>>((const float4*)w2, (uint2*)w2h_p, NEXP*IDIM*HDIM/4);
    cudaEventRecord(ev2, s2);

    // ---- main stream: routing chain ----
    cudaMemsetAsync(out, 0, (size_t)T * HDIM * sizeof(float));
    init_kernel<<<(MAX_ROWS + 255)/256, 256>>>();
    router_kernel<<<(T + 7)/8, 256>>>(x, rw, rb, T);
    offsets_kernel<<<1, 1>>>();
    fill_kernel<<<(T*TOPK + 255)/256, 256>>>(T);

    // ---- join ----
    cudaStreamWaitEvent(0, ev1, 0);
    gemm1_kernel<<<dim3(IDIM/BN1, MAX_TILES), 256, SMEM1>>>(b1);
    cudaStreamWaitEvent(0, ev2, 0);
    gemm2_kernel<<<dim3(HDIM/BN2, MAX_TILES), 256, SMEM2>>>(b2, out);
}